// round 14
// baseline (speedup 1.0000x reference)
#include <cuda_runtime.h>
#include <cuda_fp16.h>
#include <cstdint>

// Problem constants
#define TT 500
#define BB 32
#define INF 512
#define HH 1024
#define G4 4096
#define H2 2048
#define NBLK2 128

// gx packed fp16: [dir][t][b][jp(512)] -> uint4 of 8 halves {i0,i1,f0,f1,c0,c1,o0,o1}
__device__ uint4 g_gxh[(size_t)2 * TT * BB * 512];
// W_hh fp16 A-fragments: [dir][mt(256)][kA(64)][lane(32)] uint4 ; row=4j+gate
__device__ uint4 g_ap[2 * 256 * 64 * 32];
// h fp16 B-fragments: [buf(2)][dir(2)][kA(64)][seg(2)][half(2)][lane(32)] uint4
__device__ uint4 g_hp[2 * 2 * 64 * 2 * 2 * 32];
// x fp16 A-fragments: [mt(1000)][kA(32)][lane(32)] uint4
__device__ uint4 g_xa[1000 * 32 * 32];
// w_ih fp16 B-fragments: [dir][nt(128)][kA(32)][half(2)][lane(32)] uint4
__device__ uint4 g_wb[2 * 128 * 32 * 2 * 32];
// dataflow counters, one L2 line each: [dir(2)][quarter(4)] stride 32
__device__ unsigned g_prod[2 * 4 * 32];    // h produced (per quarter)
__device__ unsigned g_stage[2 * 4 * 32];   // quarter staged by a CTA

__device__ __forceinline__ float hsig(float x) {
    return fminf(fmaxf(0.2f * x + 0.5f, 0.0f), 1.0f);
}
__device__ __forceinline__ float htanh(float x) {
    return fminf(fmaxf(x, -1.0f), 1.0f);
}
__device__ __forceinline__ void mma16816(float* c, const uint4& a,
                                         uint32_t b0, uint32_t b1) {
    asm volatile(
        "mma.sync.aligned.m16n8k16.row.col.f32.f16.f16.f32 "
        "{%0,%1,%2,%3}, {%4,%5,%6,%7}, {%8,%9}, {%0,%1,%2,%3};"
        : "+f"(c[0]), "+f"(c[1]), "+f"(c[2]), "+f"(c[3])
        : "r"(a.x), "r"(a.y), "r"(a.z), "r"(a.w), "r"(b0), "r"(b1));
}
__device__ __forceinline__ uint32_t smaddr(const void* p) {
    uint32_t a;
    asm("{ .reg .u64 t; cvta.to.shared.u64 t, %1; cvt.u32.u64 %0, t; }"
        : "=r"(a) : "l"(p));
    return a;
}
__device__ __forceinline__ void cpa16(uint32_t s, const void* g) {
    asm volatile("cp.async.cg.shared.global [%0], [%1], 16;" :: "r"(s), "l"(g));
}
__device__ __forceinline__ void cpa_commit() {
    asm volatile("cp.async.commit_group;");
}
template <int N>
__device__ __forceinline__ void cpa_wait() {
    asm volatile("cp.async.wait_group %0;" :: "n"(N));
}
__device__ __forceinline__ uint16_t f2h(float v) {
    return __half_as_ushort(__float2half_rn(v));
}
__device__ __forceinline__ uint32_t pack2h(float a, float b) {
    return (uint32_t)f2h(a) | ((uint32_t)f2h(b) << 16);
}
__device__ __forceinline__ float2 h2f2(uint32_t u) {
    __half2 h;
    *reinterpret_cast<uint32_t*>(&h) = u;
    return __half22float2(h);
}

// ---------------------------------------------------------------------------
// Prepack w_hh -> fp16 A-fragments (proven).
// ---------------------------------------------------------------------------
__global__ void prepack_a(const float* __restrict__ whh_f,
                          const float* __restrict__ whh_r) {
    const int id = blockIdx.x * blockDim.x + threadIdx.x;
    const int lane = id & 31;
    const int kA = (id >> 5) & 63;
    const int mt = (id >> 11) & 255;
    const int dir = id >> 19;
    const float* __restrict__ w = dir ? whh_r : whh_f;
    const int g = lane >> 2, tq = lane & 3;
    const int rbase = mt * 16 + g;
    const int k0 = kA * 16 + 2 * tq;

    uint32_t outw[4];
#pragma unroll
    for (int pos = 0; pos < 4; ++pos) {
        const int row = rbase + (pos & 1) * 8;
        const int kk = k0 + (pos >> 1) * 8;
        const int j = row >> 2, gate = row & 3;
        const float* wrow = w + (size_t)(gate * HH + j) * HH;
        outw[pos] = pack2h(wrow[kk], wrow[kk + 1]);
    }
    g_ap[id] = make_uint4(outw[0], outw[1], outw[2], outw[3]);
}

// ---------------------------------------------------------------------------
// Prepack x -> fp16 A-fragments (proven).
// ---------------------------------------------------------------------------
__global__ void prepack_x(const float* __restrict__ x) {
    const int id = blockIdx.x * blockDim.x + threadIdx.x;
    if (id >= 1000 * 32 * 32) return;
    const int lane = id & 31;
    const int kA = (id >> 5) & 31;
    const int mt = id >> 10;
    const int g = lane >> 2, tq = lane & 3;
    const int m0 = mt * 16 + g;
    const int k0 = kA * 16 + 2 * tq;

    uint32_t outw[4];
#pragma unroll
    for (int pos = 0; pos < 4; ++pos) {
        const int m = m0 + (pos & 1) * 8;
        const int kk = k0 + (pos >> 1) * 8;
        const float* xr = x + (size_t)m * INF;
        outw[pos] = pack2h(xr[kk], xr[kk + 1]);
    }
    g_xa[id] = make_uint4(outw[0], outw[1], outw[2], outw[3]);
}

// ---------------------------------------------------------------------------
// Prepack w_ih -> fp16 B-fragments (proven).
// ---------------------------------------------------------------------------
__global__ void prepack_wb(const float* __restrict__ wih_f,
                           const float* __restrict__ wih_r) {
    const int id = blockIdx.x * blockDim.x + threadIdx.x;
    const int sub = id & 3;
    const int laneW = (id >> 2) & 31;
    const int half = (id >> 7) & 1;
    const int kA = (id >> 8) & 31;
    const int nt = (id >> 13) & 127;
    const int dir = id >> 20;
    const float* __restrict__ w = dir ? wih_r : wih_f;

    const int wd = half * 4 + sub;
    const int ip = (wd & 1) * 4 + (laneW & 3);
    const int nl = (wd >> 1) * 8 + (laneW >> 2);
    const int n = nt * 32 + nl;
    const int k = kA * 16 + ip * 2;
    const float* wr = w + (size_t)n * INF;
    reinterpret_cast<uint32_t*>(g_wb)[id] = pack2h(wr[k], wr[k + 1]);
}

// ---------------------------------------------------------------------------
__global__ void init_kernel() {
    const int id = blockIdx.x * blockDim.x + threadIdx.x;
    if (id < 2 * 2 * 64 * 2 * 2 * 32) g_hp[id] = make_uint4(0u, 0u, 0u, 0u);
    if (id < 2 * 4 * 32) { g_prod[id] = 0u; g_stage[id] = 0u; }
}

// ---------------------------------------------------------------------------
// gx GEMM via fp16 mma.sync; epilogue stores PACKED FP16 gx (proven).
// ---------------------------------------------------------------------------
__global__ void __launch_bounds__(256)
gemm_gx(const float* __restrict__ bih_f, const float* __restrict__ bhh_f,
        const float* __restrict__ bih_r, const float* __restrict__ bhh_r) {
    extern __shared__ uint4 sm[];
    const uint32_t sbase = smaddr(sm);

    const int tid = threadIdx.x;
    const int lane = tid & 31;
    const int wid = tid >> 5;
    const int mw = wid >> 2, nw = wid & 3;
    const int dir = blockIdx.x >> 5;
    const int nti = blockIdx.x & 31;
    const int mt0 = blockIdx.y * 8;
    const int nt0 = nti * 4;

    const float* __restrict__ b1 = dir ? bih_r : bih_f;
    const float* __restrict__ b2 = dir ? bhh_r : bhh_f;
    uint32_t* __restrict__ gxw =
        reinterpret_cast<uint32_t*>(g_gxh) + (size_t)dir * TT * BB * 2048;

    auto load_chunk = [&](int c, int buf) {
        const int kA0 = c * 8;
#pragma unroll
        for (int i = 0; i < 8; ++i) {
            const int idx = tid + i * 256;
            const int mtl = idx >> 8;
            const int kAl = (idx >> 5) & 7;
            const int l = idx & 31;
            const uint4* src = g_xa + ((size_t)(mt0 + mtl) * 32 + kA0 + kAl) * 32 + l;
            cpa16(sbase + (buf * 2048 + idx) * 16, src);
        }
#pragma unroll
        for (int i = 0; i < 8; ++i) {
            const int idx = tid + i * 256;
            const int ntl = idx >> 9;
            const int kAl = (idx >> 6) & 7;
            const int hf = (idx >> 5) & 1;
            const int l = idx & 31;
            const uint4* src =
                g_wb + ((((size_t)(dir * 128 + nt0 + ntl) * 32 + kA0 + kAl) * 2 + hf)) * 32 + l;
            cpa16(sbase + (4096 + buf * 2048 + idx) * 16, src);
        }
        cpa_commit();
    };

    float acc[4][4][4] = {};

    load_chunk(0, 0);
    load_chunk(1, 1);

#pragma unroll 1
    for (int c = 0; c < 4; ++c) {
        cpa_wait<1>();
        __syncthreads();
        const int buf = c & 1;
        const uint4* Asm = sm + buf * 2048;
        const uint4* Bsm = sm + 4096 + buf * 2048;
#pragma unroll
        for (int kAl = 0; kAl < 8; ++kAl) {
            uint4 af[4];
#pragma unroll
            for (int i = 0; i < 4; ++i)
                af[i] = Asm[((mw * 4 + i) * 8 + kAl) * 32 + lane];
            uint4 bf0 = Bsm[((nw * 8 + kAl) * 2 + 0) * 32 + lane];
            uint4 bf1 = Bsm[((nw * 8 + kAl) * 2 + 1) * 32 + lane];
#pragma unroll
            for (int i = 0; i < 4; ++i) {
                mma16816(acc[i][0], af[i], bf0.x, bf0.y);
                mma16816(acc[i][1], af[i], bf0.z, bf0.w);
                mma16816(acc[i][2], af[i], bf1.x, bf1.y);
                mma16816(acc[i][3], af[i], bf1.z, bf1.w);
            }
        }
        __syncthreads();
        if (c + 2 < 4) load_chunk(c + 2, buf);
    }

    const int g = lane >> 2, q = lane & 3;
#pragma unroll
    for (int i = 0; i < 4; ++i) {
        const int m = blockIdx.y * 128 + mw * 64 + i * 16 + g;
#pragma unroll
        for (int nt = 0; nt < 4; ++nt) {
            const int nd = nti * 128 + nw * 32 + nt * 8 + q * 2;
            const int gate = nd >> 10;
            const int j = nd & 1023;
            const int jp = j >> 1;
            const float bias0 = __ldg(&b1[nd]) + __ldg(&b2[nd]);
            const float bias1 = __ldg(&b1[nd + 1]) + __ldg(&b2[nd + 1]);
#pragma unroll
            for (int hrow = 0; hrow < 2; ++hrow) {
                const int mm = m + hrow * 8;
                const int tt = mm >> 5, bb = mm & 31;
                gxw[(((size_t)tt * BB + bb) * 512 + jp) * 4 + gate] =
                    pack2h(acc[i][nt][hrow * 2] + bias0,
                           acc[i][nt][hrow * 2 + 1] + bias1);
            }
        }
    }
}

// ---------------------------------------------------------------------------
// Persistent weight-stationary recurrence with QUARTER-SCOPED dataflow sync.
// CTA ct produces h fragment row kA = ct (quarter ct>>4); warp-quarter s
// consumes only kA in [16s,16s+16) -> 16 producer CTAs. No global barrier.
//   prod_cnt[dir][q]  : arrivals after h-store; staging of quarter s polls 16*t.
//   stage_cnt[dir][q] : arrivals after quarter staged; h-store polls 64*t
//                       (write-after-read guard on the double buffer).
// All polls are VOLATILE on the RMW'd location (R12-proven causality).
// ---------------------------------------------------------------------------
#define SH_U4 8192
#define PSM_BYTES (SH_U4 * 16 + 4 * 64 * 33 * 4)

__global__ void __launch_bounds__(256, 1)
lstm_persist(float* __restrict__ out) {
    extern __shared__ uint4 sm2[];
    uint4* sH = sm2;
    float* sDf = (float*)(sm2 + SH_U4);
    const uint32_t sHaddr = smaddr(sH);

    const int tid = threadIdx.x;
    const int lane = tid & 31;
    const int wid = tid >> 5;
    const int s = wid & 3;        // K-quarter
    const int rg = wid >> 2;      // row group
    const int dir = blockIdx.x >> 6;
    const int ct = blockIdx.x & 63;
    const int myq = ct >> 4;      // quarter this CTA's h output belongs to

    // Load A fragments into registers once: 2 row-tiles x 16 kA.
    uint4 areg[2][16];
#pragma unroll
    for (int i2 = 0; i2 < 2; ++i2) {
        const int mtl = rg * 2 + i2;
        const uint4* Ap =
            g_ap + (((size_t)(dir * 256 + ct * 4 + mtl) * 64) + s * 16) * 32 + lane;
#pragma unroll
        for (int kl = 0; kl < 16; ++kl) areg[i2][kl] = __ldg(Ap + kl * 32);
    }

    // Epilogue slot: thread -> (jpair jp, batch eb).
    const int eb = tid & 31;
    const int jp = tid >> 5;
    const int jg = ct * 16 + jp * 2;
    float2 creg = make_float2(0.f, 0.f);
    float2 hlast = make_float2(0.f, 0.f);

    uint32_t* __restrict__ hpw = reinterpret_cast<uint32_t*>(g_hp);
    const uint4* __restrict__ gxd = g_gxh + (size_t)dir * TT * BB * 512;
    unsigned* __restrict__ prodc  = &g_prod[(dir * 4 + s) * 32];     // staging wait
    unsigned* __restrict__ prodme = &g_prod[(dir * 4 + myq) * 32];   // arrival
    unsigned* __restrict__ stagec = &g_stage[(dir * 4 + s) * 32];    // arrival
    unsigned* __restrict__ stagme = &g_stage[(dir * 4 + myq) * 32];  // h-store wait

    // Prefetch gx for t = 0.
    const int slotoff = ct * 8 + jp;
    uint4 gxv;
    {
        const int tr0 = dir ? (TT - 1) : 0;
        gxv = __ldg(gxd + ((size_t)tr0 * BB + eb) * 512 + slotoff);
    }

#pragma unroll 1
    for (int t = 0; t < TT; ++t) {
        const int rb = t & 1, wb = rb ^ 1;
        const int tr = dir ? (TT - 1 - t) : t;

        // Wait for the 16 producers of quarter s (per-warp, volatile poll).
        {
            const unsigned ptarget = 16u * (unsigned)t;
            volatile unsigned* pp = prodc;
            while (*pp < ptarget) {}
        }
        __threadfence();

        // Stage this warp-pair's h quarter (kA s*16..s*16+15) into smem.
        {
            const size_t gbase = (size_t)(rb * 2 + dir) * SH_U4;
            const int cbase = s * 2048 + rg * 1024;
#pragma unroll
            for (int i = 0; i < 32; ++i) {
                const int idx = cbase + i * 32 + lane;
                cpa16(sHaddr + idx * 16, g_hp + gbase + idx);
            }
            cpa_commit();
            cpa_wait<0>();
            asm volatile("bar.sync %0, 64;" :: "r"(s + 1) : "memory");
        }
        // Quarter s fully staged in this CTA (reads of g_hp complete).
        if (rg == 0 && lane == 0) atomicAdd(stagec, 1u);

        float acc[2][4][4] = {};

        // MMA over 16 kA, double-buffered smem fragment loads.
        {
            const uint4* Bq = sH + (s * 16) * 128;
            uint4 pb0[4], pb1[4];
#pragma unroll
            for (int s2 = 0; s2 < 4; ++s2) pb0[s2] = Bq[s2 * 32 + lane];
#pragma unroll
            for (int kl = 0; kl < 16; ++kl) {
                uint4* cur = (kl & 1) ? pb1 : pb0;
                uint4* nxt = (kl & 1) ? pb0 : pb1;
                if (kl + 1 < 16) {
#pragma unroll
                    for (int s2 = 0; s2 < 4; ++s2)
                        nxt[s2] = Bq[(kl + 1) * 128 + s2 * 32 + lane];
                }
#pragma unroll
                for (int i2 = 0; i2 < 2; ++i2) {
                    const uint4 a = areg[i2][kl];
                    mma16816(acc[i2][0], a, cur[0].x, cur[0].y);
                    mma16816(acc[i2][1], a, cur[0].z, cur[0].w);
                    mma16816(acc[i2][2], a, cur[1].x, cur[1].y);
                    mma16816(acc[i2][3], a, cur[1].z, cur[1].w);
                    mma16816(acc[i2][0], a, cur[2].x, cur[2].y);
                    mma16816(acc[i2][1], a, cur[2].z, cur[2].w);
                    mma16816(acc[i2][2], a, cur[3].x, cur[3].y);
                    mma16816(acc[i2][3], a, cur[3].z, cur[3].w);
                }
            }
        }

        // D -> smem (4 K-slices).
        {
            const int g = lane >> 2, tq = lane & 3;
#pragma unroll
            for (int i2 = 0; i2 < 2; ++i2) {
                const int rbse = (rg * 2 + i2) * 16;
#pragma unroll
                for (int nt = 0; nt < 4; ++nt) {
                    sDf[(s * 64 + rbse + g) * 33 + nt * 8 + 2 * tq] = acc[i2][nt][0];
                    sDf[(s * 64 + rbse + g) * 33 + nt * 8 + 2 * tq + 1] = acc[i2][nt][1];
                    sDf[(s * 64 + rbse + g + 8) * 33 + nt * 8 + 2 * tq] = acc[i2][nt][2];
                    sDf[(s * 64 + rbse + g + 8) * 33 + nt * 8 + 2 * tq + 1] = acc[i2][nt][3];
                }
            }
        }
        __syncthreads();

        // Epilogue: reduce 4 K-slices, gates, cell update, write h.
        {
            const int jl0 = jp * 2;
            float d[8];
#pragma unroll
            for (int q = 0; q < 8; ++q) {
                float v = 0.f;
#pragma unroll
                for (int sl = 0; sl < 4; ++sl)
                    v += sDf[(sl * 64 + jl0 * 4 + q) * 33 + eb];
                d[q] = v;
            }

            const float2 xi = h2f2(gxv.x);
            const float2 xf = h2f2(gxv.y);
            const float2 xg = h2f2(gxv.z);
            const float2 xo = h2f2(gxv.w);

            const float i0 = hsig(d[0] + xi.x);
            const float f0 = hsig(d[1] + xf.x);
            const float g0 = htanh(d[2] + xg.x);
            const float o0 = hsig(d[3] + xo.x);
            const float c0 = f0 * creg.x + i0 * g0;
            const float h0 = o0 * htanh(c0);

            const float i1 = hsig(d[4] + xi.y);
            const float f1 = hsig(d[5] + xf.y);
            const float g1 = htanh(d[6] + xg.y);
            const float o1 = hsig(d[7] + xo.y);
            const float c1 = f1 * creg.y + i1 * g1;
            const float h1 = o1 * htanh(c1);

            creg = make_float2(c0, c1);
            hlast = make_float2(h0, h1);
            *(float2*)&out[((size_t)tr * BB + eb) * H2 + dir * HH + jg] = hlast;

            const uint32_t hiw = pack2h(h0, h1);
            const float r0 = h0 - __half2float(__float2half_rn(h0));
            const float r1 = h1 - __half2float(__float2half_rn(h1));
            const uint32_t low = pack2h(r0, r1);

            const int ks = jg >> 4;
            const int rem = jg & 15;
            const int laneW = (eb & 7) * 4 + ((rem >> 1) & 3);
            const int word = (eb >> 3) * 2 + ((rem >> 3) & 1);
            const int half = word >> 2, sub = word & 3;
            const size_t base =
                (((((size_t)(wb * 2 + dir) * 64 + ks) * 2) * 2 + half) * 32 + laneW) * 4 + sub;

            // Write-after-read guard: all 64 CTAs must have staged quarter
            // myq for step t before we overwrite buffer wb.
            {
                const unsigned starget = 64u * (unsigned)t;
                volatile unsigned* sp = stagme;
                while (*sp < starget) {}
            }
            __threadfence();

            hpw[base] = hiw;           // seg 0 (hi)
            hpw[base + 256] = low;     // seg 1 (lo)
        }

        // Prefetch next step's gx (constant data; overlaps sync below).
        {
            const int tn = (t + 1 < TT) ? t + 1 : t;
            const int trn = dir ? (TT - 1 - tn) : tn;
            gxv = __ldg(gxd + ((size_t)trn * BB + eb) * 512 + slotoff);
        }

        // Publish h production for this quarter (fence -> sync -> one RMW).
        __threadfence();
        __syncthreads();
        if (tid == 0) atomicAdd(prodme, 1u);
    }

    // hy / cy tail.
    {
        const size_t obase = (size_t)TT * BB * H2;
        *(float2*)&out[obase + ((size_t)dir * BB + eb) * HH + jg] = hlast;
        *(float2*)&out[obase + 2 * BB * HH + ((size_t)dir * BB + eb) * HH + jg] = creg;
    }
}

// ---------------------------------------------------------------------------
extern "C" void kernel_launch(void* const* d_in, const int* in_sizes, int n_in,
                              void* d_out, int out_size) {
    const float* x     = (const float*)d_in[0];
    const float* wih_f = (const float*)d_in[1];
    const float* whh_f = (const float*)d_in[2];
    const float* bih_f = (const float*)d_in[3];
    const float* bhh_f = (const float*)d_in[4];
    const float* wih_r = (const float*)d_in[5];
    const float* whh_r = (const float*)d_in[6];
    const float* bih_r = (const float*)d_in[7];
    const float* bhh_r = (const float*)d_in[8];
    float* out = (float*)d_out;

    const int gemm_smem = 8192 * 16;  // 128 KB
    cudaFuncSetAttribute(gemm_gx,
                         cudaFuncAttributeMaxDynamicSharedMemorySize, gemm_smem);
    cudaFuncSetAttribute(lstm_persist,
                         cudaFuncAttributeMaxDynamicSharedMemorySize, PSM_BYTES);

    prepack_a<<<4096, 256>>>(whh_f, whh_r);
    prepack_x<<<4000, 256>>>(x);
    prepack_wb<<<8192, 256>>>(wih_f, wih_r);
    init_kernel<<<256, 256>>>();

    gemm_gx<<<dim3(64, 125), 256, gemm_smem>>>(bih_f, bhh_f, bih_r, bhh_r);

    lstm_persist<<<NBLK2, 256, PSM_BYTES>>>(out);
}

// round 15
// speedup vs baseline: 1.3574x; 1.3574x over previous
#include <cuda_runtime.h>
#include <cuda_fp16.h>
#include <cstdint>

// Problem constants
#define TT 500
#define BB 32
#define INF 512
#define HH 1024
#define G4 4096
#define H2 2048
#define NBLK2 128

// gx packed fp16: [dir][t][b][jp(512)] -> uint4 of 8 halves {i0,i1,f0,f1,c0,c1,o0,o1}
__device__ uint4 g_gxh[(size_t)2 * TT * BB * 512];
// W_hh fp16 A-fragments: [dir][mt(256)][kA(64)][lane(32)] uint4 ; row=4j+gate
__device__ uint4 g_ap[2 * 256 * 64 * 32];
// h fp16 B-fragments (single fp16, no lo): [buf(2)][dir(2)][kA(64)][half(2)][lane(32)] uint4
__device__ uint4 g_hp[2 * 2 * 64 * 2 * 32];
// x fp16 A-fragments: [mt(1000)][kA(32)][lane(32)] uint4
__device__ uint4 g_xa[1000 * 32 * 32];
// w_ih fp16 B-fragments: [dir][nt(128)][kA(32)][half(2)][lane(32)] uint4
__device__ uint4 g_wb[2 * 128 * 32 * 2 * 32];
// barrier state: per-direction arrival counter (padded to separate L2 lines)
__device__ unsigned g_cnt[2 * 32];

__device__ __forceinline__ float hsig(float x) {
    return fminf(fmaxf(0.2f * x + 0.5f, 0.0f), 1.0f);
}
__device__ __forceinline__ float htanh(float x) {
    return fminf(fmaxf(x, -1.0f), 1.0f);
}
__device__ __forceinline__ void mma16816(float* c, const uint4& a,
                                         uint32_t b0, uint32_t b1) {
    asm volatile(
        "mma.sync.aligned.m16n8k16.row.col.f32.f16.f16.f32 "
        "{%0,%1,%2,%3}, {%4,%5,%6,%7}, {%8,%9}, {%0,%1,%2,%3};"
        : "+f"(c[0]), "+f"(c[1]), "+f"(c[2]), "+f"(c[3])
        : "r"(a.x), "r"(a.y), "r"(a.z), "r"(a.w), "r"(b0), "r"(b1));
}
__device__ __forceinline__ uint32_t smaddr(const void* p) {
    uint32_t a;
    asm("{ .reg .u64 t; cvta.to.shared.u64 t, %1; cvt.u32.u64 %0, t; }"
        : "=r"(a) : "l"(p));
    return a;
}
__device__ __forceinline__ void cpa16(uint32_t s, const void* g) {
    asm volatile("cp.async.cg.shared.global [%0], [%1], 16;" :: "r"(s), "l"(g));
}
__device__ __forceinline__ void cpa_commit() {
    asm volatile("cp.async.commit_group;");
}
template <int N>
__device__ __forceinline__ void cpa_wait() {
    asm volatile("cp.async.wait_group %0;" :: "n"(N));
}
__device__ __forceinline__ uint16_t f2h(float v) {
    return __half_as_ushort(__float2half_rn(v));
}
__device__ __forceinline__ uint32_t pack2h(float a, float b) {
    return (uint32_t)f2h(a) | ((uint32_t)f2h(b) << 16);
}
__device__ __forceinline__ float2 h2f2(uint32_t u) {
    __half2 h;
    *reinterpret_cast<uint32_t*>(&h) = u;
    return __half22float2(h);
}

// ---------------------------------------------------------------------------
// Prepack w_hh -> fp16 A-fragments (proven).
// ---------------------------------------------------------------------------
__global__ void prepack_a(const float* __restrict__ whh_f,
                          const float* __restrict__ whh_r) {
    const int id = blockIdx.x * blockDim.x + threadIdx.x;
    const int lane = id & 31;
    const int kA = (id >> 5) & 63;
    const int mt = (id >> 11) & 255;
    const int dir = id >> 19;
    const float* __restrict__ w = dir ? whh_r : whh_f;
    const int g = lane >> 2, tq = lane & 3;
    const int rbase = mt * 16 + g;
    const int k0 = kA * 16 + 2 * tq;

    uint32_t outw[4];
#pragma unroll
    for (int pos = 0; pos < 4; ++pos) {
        const int row = rbase + (pos & 1) * 8;
        const int kk = k0 + (pos >> 1) * 8;
        const int j = row >> 2, gate = row & 3;
        const float* wrow = w + (size_t)(gate * HH + j) * HH;
        outw[pos] = pack2h(wrow[kk], wrow[kk + 1]);
    }
    g_ap[id] = make_uint4(outw[0], outw[1], outw[2], outw[3]);
}

// ---------------------------------------------------------------------------
// Prepack x -> fp16 A-fragments (proven).
// ---------------------------------------------------------------------------
__global__ void prepack_x(const float* __restrict__ x) {
    const int id = blockIdx.x * blockDim.x + threadIdx.x;
    if (id >= 1000 * 32 * 32) return;
    const int lane = id & 31;
    const int kA = (id >> 5) & 31;
    const int mt = id >> 10;
    const int g = lane >> 2, tq = lane & 3;
    const int m0 = mt * 16 + g;
    const int k0 = kA * 16 + 2 * tq;

    uint32_t outw[4];
#pragma unroll
    for (int pos = 0; pos < 4; ++pos) {
        const int m = m0 + (pos & 1) * 8;
        const int kk = k0 + (pos >> 1) * 8;
        const float* xr = x + (size_t)m * INF;
        outw[pos] = pack2h(xr[kk], xr[kk + 1]);
    }
    g_xa[id] = make_uint4(outw[0], outw[1], outw[2], outw[3]);
}

// ---------------------------------------------------------------------------
// Prepack w_ih -> fp16 B-fragments (proven).
// ---------------------------------------------------------------------------
__global__ void prepack_wb(const float* __restrict__ wih_f,
                           const float* __restrict__ wih_r) {
    const int id = blockIdx.x * blockDim.x + threadIdx.x;
    const int sub = id & 3;
    const int laneW = (id >> 2) & 31;
    const int half = (id >> 7) & 1;
    const int kA = (id >> 8) & 31;
    const int nt = (id >> 13) & 127;
    const int dir = id >> 20;
    const float* __restrict__ w = dir ? wih_r : wih_f;

    const int wd = half * 4 + sub;
    const int ip = (wd & 1) * 4 + (laneW & 3);
    const int nl = (wd >> 1) * 8 + (laneW >> 2);
    const int n = nt * 32 + nl;
    const int k = kA * 16 + ip * 2;
    const float* wr = w + (size_t)n * INF;
    reinterpret_cast<uint32_t*>(g_wb)[id] = pack2h(wr[k], wr[k + 1]);
}

// ---------------------------------------------------------------------------
__global__ void init_kernel() {
    const int id = blockIdx.x * blockDim.x + threadIdx.x;
    if (id < 2 * 2 * 64 * 2 * 32) g_hp[id] = make_uint4(0u, 0u, 0u, 0u);
    if (id < 2 * 32) g_cnt[id] = 0u;
}

// ---------------------------------------------------------------------------
// gx GEMM via fp16 mma.sync; epilogue stores PACKED FP16 gx (proven).
// ---------------------------------------------------------------------------
__global__ void __launch_bounds__(256)
gemm_gx(const float* __restrict__ bih_f, const float* __restrict__ bhh_f,
        const float* __restrict__ bih_r, const float* __restrict__ bhh_r) {
    extern __shared__ uint4 sm[];
    const uint32_t sbase = smaddr(sm);

    const int tid = threadIdx.x;
    const int lane = tid & 31;
    const int wid = tid >> 5;
    const int mw = wid >> 2, nw = wid & 3;
    const int dir = blockIdx.x >> 5;
    const int nti = blockIdx.x & 31;
    const int mt0 = blockIdx.y * 8;
    const int nt0 = nti * 4;

    const float* __restrict__ b1 = dir ? bih_r : bih_f;
    const float* __restrict__ b2 = dir ? bhh_r : bhh_f;
    uint32_t* __restrict__ gxw =
        reinterpret_cast<uint32_t*>(g_gxh) + (size_t)dir * TT * BB * 2048;

    auto load_chunk = [&](int c, int buf) {
        const int kA0 = c * 8;
#pragma unroll
        for (int i = 0; i < 8; ++i) {
            const int idx = tid + i * 256;
            const int mtl = idx >> 8;
            const int kAl = (idx >> 5) & 7;
            const int l = idx & 31;
            const uint4* src = g_xa + ((size_t)(mt0 + mtl) * 32 + kA0 + kAl) * 32 + l;
            cpa16(sbase + (buf * 2048 + idx) * 16, src);
        }
#pragma unroll
        for (int i = 0; i < 8; ++i) {
            const int idx = tid + i * 256;
            const int ntl = idx >> 9;
            const int kAl = (idx >> 6) & 7;
            const int hf = (idx >> 5) & 1;
            const int l = idx & 31;
            const uint4* src =
                g_wb + ((((size_t)(dir * 128 + nt0 + ntl) * 32 + kA0 + kAl) * 2 + hf)) * 32 + l;
            cpa16(sbase + (4096 + buf * 2048 + idx) * 16, src);
        }
        cpa_commit();
    };

    float acc[4][4][4] = {};

    load_chunk(0, 0);
    load_chunk(1, 1);

#pragma unroll 1
    for (int c = 0; c < 4; ++c) {
        cpa_wait<1>();
        __syncthreads();
        const int buf = c & 1;
        const uint4* Asm = sm + buf * 2048;
        const uint4* Bsm = sm + 4096 + buf * 2048;
#pragma unroll
        for (int kAl = 0; kAl < 8; ++kAl) {
            uint4 af[4];
#pragma unroll
            for (int i = 0; i < 4; ++i)
                af[i] = Asm[((mw * 4 + i) * 8 + kAl) * 32 + lane];
            uint4 bf0 = Bsm[((nw * 8 + kAl) * 2 + 0) * 32 + lane];
            uint4 bf1 = Bsm[((nw * 8 + kAl) * 2 + 1) * 32 + lane];
#pragma unroll
            for (int i = 0; i < 4; ++i) {
                mma16816(acc[i][0], af[i], bf0.x, bf0.y);
                mma16816(acc[i][1], af[i], bf0.z, bf0.w);
                mma16816(acc[i][2], af[i], bf1.x, bf1.y);
                mma16816(acc[i][3], af[i], bf1.z, bf1.w);
            }
        }
        __syncthreads();
        if (c + 2 < 4) load_chunk(c + 2, buf);
    }

    const int g = lane >> 2, q = lane & 3;
#pragma unroll
    for (int i = 0; i < 4; ++i) {
        const int m = blockIdx.y * 128 + mw * 64 + i * 16 + g;
#pragma unroll
        for (int nt = 0; nt < 4; ++nt) {
            const int nd = nti * 128 + nw * 32 + nt * 8 + q * 2;
            const int gate = nd >> 10;
            const int j = nd & 1023;
            const int jp = j >> 1;
            const float bias0 = __ldg(&b1[nd]) + __ldg(&b2[nd]);
            const float bias1 = __ldg(&b1[nd + 1]) + __ldg(&b2[nd + 1]);
#pragma unroll
            for (int hrow = 0; hrow < 2; ++hrow) {
                const int mm = m + hrow * 8;
                const int tt = mm >> 5, bb = mm & 31;
                gxw[(((size_t)tt * BB + bb) * 512 + jp) * 4 + gate] =
                    pack2h(acc[i][nt][hrow * 2] + bias0,
                           acc[i][nt][hrow * 2 + 1] + bias1);
            }
        }
    }
}

// ---------------------------------------------------------------------------
// Persistent weight-stationary recurrence, smem-staged SINGLE-FP16 h.
// 128 CTAs x 256 thr. R13-proven global per-dir barrier (volatile poll on the
// RMW'd counter). h lo-correction dropped: staging + MMA volume halved.
// ---------------------------------------------------------------------------
#define SH_U4 4096
#define PSM_BYTES (SH_U4 * 16 + 4 * 64 * 33 * 4)

__global__ void __launch_bounds__(256, 1)
lstm_persist(float* __restrict__ out) {
    extern __shared__ uint4 sm2[];
    uint4* sH = sm2;
    float* sDf = (float*)(sm2 + SH_U4);
    const uint32_t sHaddr = smaddr(sH);

    const int tid = threadIdx.x;
    const int lane = tid & 31;
    const int wid = tid >> 5;
    const int s = wid & 3;        // K-quarter
    const int rg = wid >> 2;      // row group
    const int dir = blockIdx.x >> 6;
    const int ct = blockIdx.x & 63;

    // Load A fragments into registers once: 2 row-tiles x 16 kA.
    uint4 areg[2][16];
#pragma unroll
    for (int i2 = 0; i2 < 2; ++i2) {
        const int mtl = rg * 2 + i2;
        const uint4* Ap =
            g_ap + (((size_t)(dir * 256 + ct * 4 + mtl) * 64) + s * 16) * 32 + lane;
#pragma unroll
        for (int kl = 0; kl < 16; ++kl) areg[i2][kl] = __ldg(Ap + kl * 32);
    }

    // Epilogue slot: thread -> (jpair jp, batch eb).
    const int eb = tid & 31;
    const int jp = tid >> 5;
    const int jg = ct * 16 + jp * 2;
    float2 creg = make_float2(0.f, 0.f);
    float2 hlast = make_float2(0.f, 0.f);

    uint32_t* __restrict__ hpw = reinterpret_cast<uint32_t*>(g_hp);
    const uint4* __restrict__ gxd = g_gxh + (size_t)dir * TT * BB * 512;
    unsigned* __restrict__ cntp = &g_cnt[dir * 32];

    // Prefetch gx for t = 0.
    const int slotoff = ct * 8 + jp;
    uint4 gxv;
    {
        const int tr0 = dir ? (TT - 1) : 0;
        gxv = __ldg(gxd + ((size_t)tr0 * BB + eb) * 512 + slotoff);
    }

#pragma unroll 1
    for (int t = 0; t < TT; ++t) {
        const int rb = t & 1, wb = rb ^ 1;
        const int tr = dir ? (TT - 1 - t) : t;

        // Stage this warp-pair's h quarter (kA s*16..s*16+15) into smem.
        // Quarter = 16 kA x 2 half x 32 lanes = 1024 uint4; each warp 512.
        {
            const size_t gbase = (size_t)(rb * 2 + dir) * SH_U4;
            const int cbase = s * 1024 + rg * 512;
#pragma unroll
            for (int i = 0; i < 16; ++i) {
                const int idx = cbase + i * 32 + lane;
                cpa16(sHaddr + idx * 16, g_hp + gbase + idx);
            }
            cpa_commit();
            cpa_wait<0>();
            asm volatile("bar.sync %0, 64;" :: "r"(s + 1) : "memory");
        }

        float acc[2][4][4] = {};

        // MMA over 16 kA, double-buffered smem fragment loads (2 u4/kA).
        {
            const uint4* Bq = sH + s * 1024;
            uint4 pb0[2], pb1[2];
#pragma unroll
            for (int s2 = 0; s2 < 2; ++s2) pb0[s2] = Bq[s2 * 32 + lane];
#pragma unroll
            for (int kl = 0; kl < 16; ++kl) {
                uint4* cur = (kl & 1) ? pb1 : pb0;
                uint4* nxt = (kl & 1) ? pb0 : pb1;
                if (kl + 1 < 16) {
#pragma unroll
                    for (int s2 = 0; s2 < 2; ++s2)
                        nxt[s2] = Bq[(kl + 1) * 64 + s2 * 32 + lane];
                }
#pragma unroll
                for (int i2 = 0; i2 < 2; ++i2) {
                    const uint4 a = areg[i2][kl];
                    mma16816(acc[i2][0], a, cur[0].x, cur[0].y);
                    mma16816(acc[i2][1], a, cur[0].z, cur[0].w);
                    mma16816(acc[i2][2], a, cur[1].x, cur[1].y);
                    mma16816(acc[i2][3], a, cur[1].z, cur[1].w);
                }
            }
        }

        // D -> smem (4 K-slices).
        {
            const int g = lane >> 2, tq = lane & 3;
#pragma unroll
            for (int i2 = 0; i2 < 2; ++i2) {
                const int rbse = (rg * 2 + i2) * 16;
#pragma unroll
                for (int nt = 0; nt < 4; ++nt) {
                    sDf[(s * 64 + rbse + g) * 33 + nt * 8 + 2 * tq] = acc[i2][nt][0];
                    sDf[(s * 64 + rbse + g) * 33 + nt * 8 + 2 * tq + 1] = acc[i2][nt][1];
                    sDf[(s * 64 + rbse + g + 8) * 33 + nt * 8 + 2 * tq] = acc[i2][nt][2];
                    sDf[(s * 64 + rbse + g + 8) * 33 + nt * 8 + 2 * tq + 1] = acc[i2][nt][3];
                }
            }
        }
        __syncthreads();

        // Epilogue: reduce 4 K-slices, gates, cell update, write h.
        {
            const int jl0 = jp * 2;
            float d[8];
#pragma unroll
            for (int q = 0; q < 8; ++q) {
                float v = 0.f;
#pragma unroll
                for (int sl = 0; sl < 4; ++sl)
                    v += sDf[(sl * 64 + jl0 * 4 + q) * 33 + eb];
                d[q] = v;
            }

            const float2 xi = h2f2(gxv.x);
            const float2 xf = h2f2(gxv.y);
            const float2 xg = h2f2(gxv.z);
            const float2 xo = h2f2(gxv.w);

            const float i0 = hsig(d[0] + xi.x);
            const float f0 = hsig(d[1] + xf.x);
            const float g0 = htanh(d[2] + xg.x);
            const float o0 = hsig(d[3] + xo.x);
            const float c0 = f0 * creg.x + i0 * g0;
            const float h0 = o0 * htanh(c0);

            const float i1 = hsig(d[4] + xi.y);
            const float f1 = hsig(d[5] + xf.y);
            const float g1 = htanh(d[6] + xg.y);
            const float o1 = hsig(d[7] + xo.y);
            const float c1 = f1 * creg.y + i1 * g1;
            const float h1 = o1 * htanh(c1);

            creg = make_float2(c0, c1);
            hlast = make_float2(h0, h1);

            // h -> fp16 B-fragment (single fp16, critical path for peers).
            const uint32_t hiw = pack2h(h0, h1);
            const int ks = jg >> 4;
            const int rem = jg & 15;
            const int laneW = (eb & 7) * 4 + ((rem >> 1) & 3);
            const int word = (eb >> 3) * 2 + ((rem >> 3) & 1);
            const int half = word >> 2, sub = word & 3;
            const size_t base =
                ((((size_t)(wb * 2 + dir) * 64 + ks) * 2 + half) * 32 + laneW) * 4 + sub;
            hpw[base] = hiw;

            *(float2*)&out[((size_t)tr * BB + eb) * H2 + dir * HH + jg] = hlast;
        }

        // Prefetch next step's gx (constant data; overlaps barrier below).
        {
            const int tn = (t + 1 < TT) ? t + 1 : t;
            const int trn = dir ? (TT - 1 - tn) : tn;
            gxv = __ldg(gxd + ((size_t)trn * BB + eb) * 512 + slotoff);
        }

        // Per-direction barrier. Arrivals RMW the counter; waiter polls the
        // SAME location with a VOLATILE load (morally-strong per PTX memory
        // model — R12/R13-proven; weak ld.cg polls broke R9/R11).
        __threadfence();
        __syncthreads();
        if (tid == 0) {
            atomicAdd(cntp, 1u);
            const unsigned target = 64u * (unsigned)(t + 1);
            volatile unsigned* p = cntp;
            while (*p < target) {}
            __threadfence();
        }
        __syncthreads();
    }

    // hy / cy tail.
    {
        const size_t obase = (size_t)TT * BB * H2;
        *(float2*)&out[obase + ((size_t)dir * BB + eb) * HH + jg] = hlast;
        *(float2*)&out[obase + 2 * BB * HH + ((size_t)dir * BB + eb) * HH + jg] = creg;
    }
}

// ---------------------------------------------------------------------------
extern "C" void kernel_launch(void* const* d_in, const int* in_sizes, int n_in,
                              void* d_out, int out_size) {
    const float* x     = (const float*)d_in[0];
    const float* wih_f = (const float*)d_in[1];
    const float* whh_f = (const float*)d_in[2];
    const float* bih_f = (const float*)d_in[3];
    const float* bhh_f = (const float*)d_in[4];
    const float* wih_r = (const float*)d_in[5];
    const float* whh_r = (const float*)d_in[6];
    const float* bih_r = (const float*)d_in[7];
    const float* bhh_r = (const float*)d_in[8];
    float* out = (float*)d_out;

    const int gemm_smem = 8192 * 16;  // 128 KB
    cudaFuncSetAttribute(gemm_gx,
                         cudaFuncAttributeMaxDynamicSharedMemorySize, gemm_smem);
    cudaFuncSetAttribute(lstm_persist,
                         cudaFuncAttributeMaxDynamicSharedMemorySize, PSM_BYTES);

    prepack_a<<<4096, 256>>>(whh_f, whh_r);
    prepack_x<<<4000, 256>>>(x);
    prepack_wb<<<8192, 256>>>(wih_f, wih_r);
    init_kernel<<<256, 256>>>();

    gemm_gx<<<dim3(64, 125), 256, gemm_smem>>>(bih_f, bhh_f, bih_r, bhh_r);

    lstm_persist<<<NBLK2, 256, PSM_BYTES>>>(out);
}

// round 16
// speedup vs baseline: 1.3743x; 1.0125x over previous
#include <cuda_runtime.h>
#include <cuda_fp16.h>
#include <cstdint>

// Problem constants
#define TT 500
#define BB 32
#define INF 512
#define HH 1024
#define G4 4096
#define H2 2048
#define NBLK2 128

// gx packed fp16: [dir][t][b][jp(512)] -> uint4 of 8 halves {i0,i1,f0,f1,c0,c1,o0,o1}
__device__ uint4 g_gxh[(size_t)2 * TT * BB * 512];
// W_hh fp16 A-fragments: [dir][mt(256)][kA(64)][lane(32)] uint4 ; row=4j+gate
__device__ uint4 g_ap[2 * 256 * 64 * 32];
// h fp16 B-fragments (single fp16): [buf(2)][dir(2)][kA(64)][half(2)][lane(32)] uint4
__device__ uint4 g_hp[2 * 2 * 64 * 2 * 32];
// x fp16 A-fragments: [mt(1000)][kA(32)][lane(32)] uint4
__device__ uint4 g_xa[1000 * 32 * 32];
// w_ih fp16 B-fragments: [dir][nt(128)][kA(32)][half(2)][lane(32)] uint4
__device__ uint4 g_wb[2 * 128 * 32 * 2 * 32];
// barrier state: per-direction, 8 striped arrival counters, 128B apart
__device__ unsigned g_cnt[2 * 8 * 32];

__device__ __forceinline__ float hsig(float x) {
    return fminf(fmaxf(0.2f * x + 0.5f, 0.0f), 1.0f);
}
__device__ __forceinline__ float htanh(float x) {
    return fminf(fmaxf(x, -1.0f), 1.0f);
}
__device__ __forceinline__ void mma16816(float* c, const uint4& a,
                                         uint32_t b0, uint32_t b1) {
    asm volatile(
        "mma.sync.aligned.m16n8k16.row.col.f32.f16.f16.f32 "
        "{%0,%1,%2,%3}, {%4,%5,%6,%7}, {%8,%9}, {%0,%1,%2,%3};"
        : "+f"(c[0]), "+f"(c[1]), "+f"(c[2]), "+f"(c[3])
        : "r"(a.x), "r"(a.y), "r"(a.z), "r"(a.w), "r"(b0), "r"(b1));
}
__device__ __forceinline__ uint32_t smaddr(const void* p) {
    uint32_t a;
    asm("{ .reg .u64 t; cvta.to.shared.u64 t, %1; cvt.u32.u64 %0, t; }"
        : "=r"(a) : "l"(p));
    return a;
}
__device__ __forceinline__ void cpa16(uint32_t s, const void* g) {
    asm volatile("cp.async.cg.shared.global [%0], [%1], 16;" :: "r"(s), "l"(g));
}
__device__ __forceinline__ void cpa_commit() {
    asm volatile("cp.async.commit_group;");
}
template <int N>
__device__ __forceinline__ void cpa_wait() {
    asm volatile("cp.async.wait_group %0;" :: "n"(N));
}
__device__ __forceinline__ uint16_t f2h(float v) {
    return __half_as_ushort(__float2half_rn(v));
}
__device__ __forceinline__ uint32_t pack2h(float a, float b) {
    return (uint32_t)f2h(a) | ((uint32_t)f2h(b) << 16);
}
__device__ __forceinline__ float2 h2f2(uint32_t u) {
    __half2 h;
    *reinterpret_cast<uint32_t*>(&h) = u;
    return __half22float2(h);
}
// Morally-strong relaxed atomic load (gpu scope) — participates in causality.
__device__ __forceinline__ unsigned ld_relaxed(const unsigned* p) {
    unsigned v;
    asm volatile("ld.relaxed.gpu.u32 %0, [%1];" : "=r"(v) : "l"(p) : "memory");
    return v;
}

// ---------------------------------------------------------------------------
// Prepack w_hh -> fp16 A-fragments (proven).
// ---------------------------------------------------------------------------
__global__ void prepack_a(const float* __restrict__ whh_f,
                          const float* __restrict__ whh_r) {
    const int id = blockIdx.x * blockDim.x + threadIdx.x;
    const int lane = id & 31;
    const int kA = (id >> 5) & 63;
    const int mt = (id >> 11) & 255;
    const int dir = id >> 19;
    const float* __restrict__ w = dir ? whh_r : whh_f;
    const int g = lane >> 2, tq = lane & 3;
    const int rbase = mt * 16 + g;
    const int k0 = kA * 16 + 2 * tq;

    uint32_t outw[4];
#pragma unroll
    for (int pos = 0; pos < 4; ++pos) {
        const int row = rbase + (pos & 1) * 8;
        const int kk = k0 + (pos >> 1) * 8;
        const int j = row >> 2, gate = row & 3;
        const float* wrow = w + (size_t)(gate * HH + j) * HH;
        outw[pos] = pack2h(wrow[kk], wrow[kk + 1]);
    }
    g_ap[id] = make_uint4(outw[0], outw[1], outw[2], outw[3]);
}

// ---------------------------------------------------------------------------
// Prepack x -> fp16 A-fragments (proven).
// ---------------------------------------------------------------------------
__global__ void prepack_x(const float* __restrict__ x) {
    const int id = blockIdx.x * blockDim.x + threadIdx.x;
    if (id >= 1000 * 32 * 32) return;
    const int lane = id & 31;
    const int kA = (id >> 5) & 31;
    const int mt = id >> 10;
    const int g = lane >> 2, tq = lane & 3;
    const int m0 = mt * 16 + g;
    const int k0 = kA * 16 + 2 * tq;

    uint32_t outw[4];
#pragma unroll
    for (int pos = 0; pos < 4; ++pos) {
        const int m = m0 + (pos & 1) * 8;
        const int kk = k0 + (pos >> 1) * 8;
        const float* xr = x + (size_t)m * INF;
        outw[pos] = pack2h(xr[kk], xr[kk + 1]);
    }
    g_xa[id] = make_uint4(outw[0], outw[1], outw[2], outw[3]);
}

// ---------------------------------------------------------------------------
// Prepack w_ih -> fp16 B-fragments (proven).
// ---------------------------------------------------------------------------
__global__ void prepack_wb(const float* __restrict__ wih_f,
                           const float* __restrict__ wih_r) {
    const int id = blockIdx.x * blockDim.x + threadIdx.x;
    const int sub = id & 3;
    const int laneW = (id >> 2) & 31;
    const int half = (id >> 7) & 1;
    const int kA = (id >> 8) & 31;
    const int nt = (id >> 13) & 127;
    const int dir = id >> 20;
    const float* __restrict__ w = dir ? wih_r : wih_f;

    const int wd = half * 4 + sub;
    const int ip = (wd & 1) * 4 + (laneW & 3);
    const int nl = (wd >> 1) * 8 + (laneW >> 2);
    const int n = nt * 32 + nl;
    const int k = kA * 16 + ip * 2;
    const float* wr = w + (size_t)n * INF;
    reinterpret_cast<uint32_t*>(g_wb)[id] = pack2h(wr[k], wr[k + 1]);
}

// ---------------------------------------------------------------------------
__global__ void init_kernel() {
    const int id = blockIdx.x * blockDim.x + threadIdx.x;
    if (id < 2 * 2 * 64 * 2 * 32) g_hp[id] = make_uint4(0u, 0u, 0u, 0u);
    if (id < 2 * 8 * 32) g_cnt[id] = 0u;
}

// ---------------------------------------------------------------------------
// gx GEMM via fp16 mma.sync; epilogue stores PACKED FP16 gx (proven).
// ---------------------------------------------------------------------------
__global__ void __launch_bounds__(256)
gemm_gx(const float* __restrict__ bih_f, const float* __restrict__ bhh_f,
        const float* __restrict__ bih_r, const float* __restrict__ bhh_r) {
    extern __shared__ uint4 sm[];
    const uint32_t sbase = smaddr(sm);

    const int tid = threadIdx.x;
    const int lane = tid & 31;
    const int wid = tid >> 5;
    const int mw = wid >> 2, nw = wid & 3;
    const int dir = blockIdx.x >> 5;
    const int nti = blockIdx.x & 31;
    const int mt0 = blockIdx.y * 8;
    const int nt0 = nti * 4;

    const float* __restrict__ b1 = dir ? bih_r : bih_f;
    const float* __restrict__ b2 = dir ? bhh_r : bhh_f;
    uint32_t* __restrict__ gxw =
        reinterpret_cast<uint32_t*>(g_gxh) + (size_t)dir * TT * BB * 2048;

    auto load_chunk = [&](int c, int buf) {
        const int kA0 = c * 8;
#pragma unroll
        for (int i = 0; i < 8; ++i) {
            const int idx = tid + i * 256;
            const int mtl = idx >> 8;
            const int kAl = (idx >> 5) & 7;
            const int l = idx & 31;
            const uint4* src = g_xa + ((size_t)(mt0 + mtl) * 32 + kA0 + kAl) * 32 + l;
            cpa16(sbase + (buf * 2048 + idx) * 16, src);
        }
#pragma unroll
        for (int i = 0; i < 8; ++i) {
            const int idx = tid + i * 256;
            const int ntl = idx >> 9;
            const int kAl = (idx >> 6) & 7;
            const int hf = (idx >> 5) & 1;
            const int l = idx & 31;
            const uint4* src =
                g_wb + ((((size_t)(dir * 128 + nt0 + ntl) * 32 + kA0 + kAl) * 2 + hf)) * 32 + l;
            cpa16(sbase + (4096 + buf * 2048 + idx) * 16, src);
        }
        cpa_commit();
    };

    float acc[4][4][4] = {};

    load_chunk(0, 0);
    load_chunk(1, 1);

#pragma unroll 1
    for (int c = 0; c < 4; ++c) {
        cpa_wait<1>();
        __syncthreads();
        const int buf = c & 1;
        const uint4* Asm = sm + buf * 2048;
        const uint4* Bsm = sm + 4096 + buf * 2048;
#pragma unroll
        for (int kAl = 0; kAl < 8; ++kAl) {
            uint4 af[4];
#pragma unroll
            for (int i = 0; i < 4; ++i)
                af[i] = Asm[((mw * 4 + i) * 8 + kAl) * 32 + lane];
            uint4 bf0 = Bsm[((nw * 8 + kAl) * 2 + 0) * 32 + lane];
            uint4 bf1 = Bsm[((nw * 8 + kAl) * 2 + 1) * 32 + lane];
#pragma unroll
            for (int i = 0; i < 4; ++i) {
                mma16816(acc[i][0], af[i], bf0.x, bf0.y);
                mma16816(acc[i][1], af[i], bf0.z, bf0.w);
                mma16816(acc[i][2], af[i], bf1.x, bf1.y);
                mma16816(acc[i][3], af[i], bf1.z, bf1.w);
            }
        }
        __syncthreads();
        if (c + 2 < 4) load_chunk(c + 2, buf);
    }

    const int g = lane >> 2, q = lane & 3;
#pragma unroll
    for (int i = 0; i < 4; ++i) {
        const int m = blockIdx.y * 128 + mw * 64 + i * 16 + g;
#pragma unroll
        for (int nt = 0; nt < 4; ++nt) {
            const int nd = nti * 128 + nw * 32 + nt * 8 + q * 2;
            const int gate = nd >> 10;
            const int j = nd & 1023;
            const int jp = j >> 1;
            const float bias0 = __ldg(&b1[nd]) + __ldg(&b2[nd]);
            const float bias1 = __ldg(&b1[nd + 1]) + __ldg(&b2[nd + 1]);
#pragma unroll
            for (int hrow = 0; hrow < 2; ++hrow) {
                const int mm = m + hrow * 8;
                const int tt = mm >> 5, bb = mm & 31;
                gxw[(((size_t)tt * BB + bb) * 512 + jp) * 4 + gate] =
                    pack2h(acc[i][nt][hrow * 2] + bias0,
                           acc[i][nt][hrow * 2 + 1] + bias1);
            }
        }
    }
}

// ---------------------------------------------------------------------------
// Persistent weight-stationary recurrence, smem-staged SINGLE-FP16 h.
// 128 CTAs x 256 thr. Barrier arrivals striped over 8 L2 lines per dir
// (kills L2-atomic serialization); waiter sums 8 ld.relaxed.gpu loads
// (morally-strong). out-store + gx prefetch hidden in the poll shadow.
// ---------------------------------------------------------------------------
#define SH_U4 4096
#define PSM_BYTES (SH_U4 * 16 + 4 * 64 * 33 * 4)

__global__ void __launch_bounds__(256, 1)
lstm_persist(float* __restrict__ out) {
    extern __shared__ uint4 sm2[];
    uint4* sH = sm2;
    float* sDf = (float*)(sm2 + SH_U4);
    const uint32_t sHaddr = smaddr(sH);

    const int tid = threadIdx.x;
    const int lane = tid & 31;
    const int wid = tid >> 5;
    const int s = wid & 3;        // K-quarter
    const int rg = wid >> 2;      // row group
    const int dir = blockIdx.x >> 6;
    const int ct = blockIdx.x & 63;

    // Load A fragments into registers once: 2 row-tiles x 16 kA.
    uint4 areg[2][16];
#pragma unroll
    for (int i2 = 0; i2 < 2; ++i2) {
        const int mtl = rg * 2 + i2;
        const uint4* Ap =
            g_ap + (((size_t)(dir * 256 + ct * 4 + mtl) * 64) + s * 16) * 32 + lane;
#pragma unroll
        for (int kl = 0; kl < 16; ++kl) areg[i2][kl] = __ldg(Ap + kl * 32);
    }

    // Epilogue slot: thread -> (jpair jp, batch eb).
    const int eb = tid & 31;
    const int jp = tid >> 5;
    const int jg = ct * 16 + jp * 2;
    float2 creg = make_float2(0.f, 0.f);
    float2 hlast = make_float2(0.f, 0.f);

    uint32_t* __restrict__ hpw = reinterpret_cast<uint32_t*>(g_hp);
    const uint4* __restrict__ gxd = g_gxh + (size_t)dir * TT * BB * 512;
    unsigned* __restrict__ cbase = &g_cnt[dir * 256];           // 8 lines
    unsigned* __restrict__ cline = cbase + (ct & 7) * 32;       // my arrival line

    // Prefetch gx for t = 0.
    const int slotoff = ct * 8 + jp;
    uint4 gxv;
    {
        const int tr0 = dir ? (TT - 1) : 0;
        gxv = __ldg(gxd + ((size_t)tr0 * BB + eb) * 512 + slotoff);
    }

#pragma unroll 1
    for (int t = 0; t < TT; ++t) {
        const int rb = t & 1, wb = rb ^ 1;
        const int tr = dir ? (TT - 1 - t) : t;

        // Stage this warp-pair's h quarter (kA s*16..s*16+15) into smem.
        {
            const size_t gbase = (size_t)(rb * 2 + dir) * SH_U4;
            const int cbase2 = s * 1024 + rg * 512;
#pragma unroll
            for (int i = 0; i < 16; ++i) {
                const int idx = cbase2 + i * 32 + lane;
                cpa16(sHaddr + idx * 16, g_hp + gbase + idx);
            }
            cpa_commit();
            cpa_wait<0>();
            asm volatile("bar.sync %0, 64;" :: "r"(s + 1) : "memory");
        }

        float acc[2][4][4] = {};

        // MMA over 16 kA, double-buffered smem fragment loads (2 u4/kA).
        {
            const uint4* Bq = sH + s * 1024;
            uint4 pb0[2], pb1[2];
#pragma unroll
            for (int s2 = 0; s2 < 2; ++s2) pb0[s2] = Bq[s2 * 32 + lane];
#pragma unroll
            for (int kl = 0; kl < 16; ++kl) {
                uint4* cur = (kl & 1) ? pb1 : pb0;
                uint4* nxt = (kl & 1) ? pb0 : pb1;
                if (kl + 1 < 16) {
#pragma unroll
                    for (int s2 = 0; s2 < 2; ++s2)
                        nxt[s2] = Bq[(kl + 1) * 64 + s2 * 32 + lane];
                }
#pragma unroll
                for (int i2 = 0; i2 < 2; ++i2) {
                    const uint4 a = areg[i2][kl];
                    mma16816(acc[i2][0], a, cur[0].x, cur[0].y);
                    mma16816(acc[i2][1], a, cur[0].z, cur[0].w);
                    mma16816(acc[i2][2], a, cur[1].x, cur[1].y);
                    mma16816(acc[i2][3], a, cur[1].z, cur[1].w);
                }
            }
        }

        // D -> smem (4 K-slices).
        {
            const int g = lane >> 2, tq = lane & 3;
#pragma unroll
            for (int i2 = 0; i2 < 2; ++i2) {
                const int rbse = (rg * 2 + i2) * 16;
#pragma unroll
                for (int nt = 0; nt < 4; ++nt) {
                    sDf[(s * 64 + rbse + g) * 33 + nt * 8 + 2 * tq] = acc[i2][nt][0];
                    sDf[(s * 64 + rbse + g) * 33 + nt * 8 + 2 * tq + 1] = acc[i2][nt][1];
                    sDf[(s * 64 + rbse + g + 8) * 33 + nt * 8 + 2 * tq] = acc[i2][nt][2];
                    sDf[(s * 64 + rbse + g + 8) * 33 + nt * 8 + 2 * tq + 1] = acc[i2][nt][3];
                }
            }
        }
        __syncthreads();

        // Epilogue: reduce 4 K-slices, gates, cell update, write h fragments.
        {
            const int jl0 = jp * 2;
            float d[8];
#pragma unroll
            for (int q = 0; q < 8; ++q) {
                float v = 0.f;
#pragma unroll
                for (int sl = 0; sl < 4; ++sl)
                    v += sDf[(sl * 64 + jl0 * 4 + q) * 33 + eb];
                d[q] = v;
            }

            const float2 xi = h2f2(gxv.x);
            const float2 xf = h2f2(gxv.y);
            const float2 xg = h2f2(gxv.z);
            const float2 xo = h2f2(gxv.w);

            const float i0 = hsig(d[0] + xi.x);
            const float f0 = hsig(d[1] + xf.x);
            const float g0 = htanh(d[2] + xg.x);
            const float o0 = hsig(d[3] + xo.x);
            const float c0 = f0 * creg.x + i0 * g0;
            const float h0 = o0 * htanh(c0);

            const float i1 = hsig(d[4] + xi.y);
            const float f1 = hsig(d[5] + xf.y);
            const float g1 = htanh(d[6] + xg.y);
            const float o1 = hsig(d[7] + xo.y);
            const float c1 = f1 * creg.y + i1 * g1;
            const float h1 = o1 * htanh(c1);

            creg = make_float2(c0, c1);
            hlast = make_float2(h0, h1);

            // h -> fp16 B-fragment (peers' critical path; must precede fence).
            const uint32_t hiw = pack2h(h0, h1);
            const int ks = jg >> 4;
            const int rem = jg & 15;
            const int laneW = (eb & 7) * 4 + ((rem >> 1) & 3);
            const int word = (eb >> 3) * 2 + ((rem >> 3) & 1);
            const int half = word >> 2, sub = word & 3;
            const size_t base =
                ((((size_t)(wb * 2 + dir) * 64 + ks) * 2 + half) * 32 + laneW) * 4 + sub;
            hpw[base] = hiw;
        }

        // Barrier: fence + sync, striped arrival, then hide out-store and
        // gx prefetch under the poll. Waiter sums 8 relaxed atomic loads.
        __threadfence();
        __syncthreads();
        if (tid == 0) atomicAdd(cline, 1u);

        // Poll-shadow work (feeds nobody this step):
        *(float2*)&out[((size_t)tr * BB + eb) * H2 + dir * HH + jg] = hlast;
        {
            const int tn = (t + 1 < TT) ? t + 1 : t;
            const int trn = dir ? (TT - 1 - tn) : tn;
            gxv = __ldg(gxd + ((size_t)trn * BB + eb) * 512 + slotoff);
        }

        if (tid == 0) {
            const unsigned target = 64u * (unsigned)(t + 1);
            unsigned sum;
            do {
                sum = 0u;
#pragma unroll
                for (int i = 0; i < 8; ++i) sum += ld_relaxed(cbase + i * 32);
            } while (sum < target);
            __threadfence();
        }
        __syncthreads();
    }

    // hy / cy tail.
    {
        const size_t obase = (size_t)TT * BB * H2;
        *(float2*)&out[obase + ((size_t)dir * BB + eb) * HH + jg] = hlast;
        *(float2*)&out[obase + 2 * BB * HH + ((size_t)dir * BB + eb) * HH + jg] = creg;
    }
}

// ---------------------------------------------------------------------------
extern "C" void kernel_launch(void* const* d_in, const int* in_sizes, int n_in,
                              void* d_out, int out_size) {
    const float* x     = (const float*)d_in[0];
    const float* wih_f = (const float*)d_in[1];
    const float* whh_f = (const float*)d_in[2];
    const float* bih_f = (const float*)d_in[3];
    const float* bhh_f = (const float*)d_in[4];
    const float* wih_r = (const float*)d_in[5];
    const float* whh_r = (const float*)d_in[6];
    const float* bih_r = (const float*)d_in[7];
    const float* bhh_r = (const float*)d_in[8];
    float* out = (float*)d_out;

    const int gemm_smem = 8192 * 16;  // 128 KB
    cudaFuncSetAttribute(gemm_gx,
                         cudaFuncAttributeMaxDynamicSharedMemorySize, gemm_smem);
    cudaFuncSetAttribute(lstm_persist,
                         cudaFuncAttributeMaxDynamicSharedMemorySize, PSM_BYTES);

    prepack_a<<<4096, 256>>>(whh_f, whh_r);
    prepack_x<<<4000, 256>>>(x);
    prepack_wb<<<8192, 256>>>(wih_f, wih_r);
    init_kernel<<<256, 256>>>();

    gemm_gx<<<dim3(64, 125), 256, gemm_smem>>>(bih_f, bhh_f, bih_r, bhh_r);

    lstm_persist<<<NBLK2, 256, PSM_BYTES>>>(out);
}

// round 17
// speedup vs baseline: 1.5422x; 1.1221x over previous
#include <cuda_runtime.h>
#include <cuda_fp16.h>
#include <cstdint>

// Problem constants
#define TT 500
#define BB 32
#define INF 512
#define HH 1024
#define G4 4096
#define H2 2048
#define NBLK2 128

// gx packed fp16: [dir][t][b][jp(512)] -> uint4 of 8 halves {i0,i1,f0,f1,c0,c1,o0,o1}
__device__ uint4 g_gxh[(size_t)2 * TT * BB * 512];
// W_hh fp16 A-fragments: [dir][mt(256)][kA(64)][lane(32)] uint4 ; row=4j+gate
__device__ uint4 g_ap[2 * 256 * 64 * 32];
// h fp16 B-fragments (single fp16): [buf(2)][dir(2)][kA(64)][half(2)][lane(32)] uint4
__device__ uint4 g_hp[2 * 2 * 64 * 2 * 32];
// x fp16 A-fragments: [mt(1000)][kA(32)][lane(32)] uint4
__device__ uint4 g_xa[1000 * 32 * 32];
// w_ih fp16 B-fragments: [dir][nt(128)][kA(32)][half(2)][lane(32)] uint4
__device__ uint4 g_wb[2 * 128 * 32 * 2 * 32];
// barrier state: per-direction arrival counter (separate L2 lines)
__device__ unsigned g_cnt[2 * 32];

__device__ __forceinline__ float hsig(float x) {
    return fminf(fmaxf(0.2f * x + 0.5f, 0.0f), 1.0f);
}
__device__ __forceinline__ float htanh(float x) {
    return fminf(fmaxf(x, -1.0f), 1.0f);
}
__device__ __forceinline__ void mma16816(float* c, const uint4& a,
                                         uint32_t b0, uint32_t b1) {
    asm volatile(
        "mma.sync.aligned.m16n8k16.row.col.f32.f16.f16.f32 "
        "{%0,%1,%2,%3}, {%4,%5,%6,%7}, {%8,%9}, {%0,%1,%2,%3};"
        : "+f"(c[0]), "+f"(c[1]), "+f"(c[2]), "+f"(c[3])
        : "r"(a.x), "r"(a.y), "r"(a.z), "r"(a.w), "r"(b0), "r"(b1));
}
__device__ __forceinline__ uint32_t smaddr(const void* p) {
    uint32_t a;
    asm("{ .reg .u64 t; cvta.to.shared.u64 t, %1; cvt.u32.u64 %0, t; }"
        : "=r"(a) : "l"(p));
    return a;
}
__device__ __forceinline__ void cpa16(uint32_t s, const void* g) {
    asm volatile("cp.async.cg.shared.global [%0], [%1], 16;" :: "r"(s), "l"(g));
}
__device__ __forceinline__ void cpa_commit() {
    asm volatile("cp.async.commit_group;");
}
template <int N>
__device__ __forceinline__ void cpa_wait() {
    asm volatile("cp.async.wait_group %0;" :: "n"(N));
}
__device__ __forceinline__ uint16_t f2h(float v) {
    return __half_as_ushort(__float2half_rn(v));
}
__device__ __forceinline__ uint32_t pack2h(float a, float b) {
    return (uint32_t)f2h(a) | ((uint32_t)f2h(b) << 16);
}
__device__ __forceinline__ float2 h2f2(uint32_t u) {
    __half2 h;
    *reinterpret_cast<uint32_t*>(&h) = u;
    return __half22float2(h);
}
// Release arrival: orders all CTA-prior stores (via preceding bar.sync)
// before the increment becomes visible.
__device__ __forceinline__ void arrive_release(unsigned* p) {
    unsigned old;
    asm volatile("atom.add.release.gpu.u32 %0, [%1], 1;"
                 : "=r"(old) : "l"(p) : "memory");
}
// Acquire poll load: synchronizes-with the release arrivals.
__device__ __forceinline__ unsigned ld_acquire(const unsigned* p) {
    unsigned v;
    asm volatile("ld.acquire.gpu.u32 %0, [%1];" : "=r"(v) : "l"(p) : "memory");
    return v;
}

// ---------------------------------------------------------------------------
// Prepack w_hh -> fp16 A-fragments (proven).
// ---------------------------------------------------------------------------
__global__ void prepack_a(const float* __restrict__ whh_f,
                          const float* __restrict__ whh_r) {
    const int id = blockIdx.x * blockDim.x + threadIdx.x;
    const int lane = id & 31;
    const int kA = (id >> 5) & 63;
    const int mt = (id >> 11) & 255;
    const int dir = id >> 19;
    const float* __restrict__ w = dir ? whh_r : whh_f;
    const int g = lane >> 2, tq = lane & 3;
    const int rbase = mt * 16 + g;
    const int k0 = kA * 16 + 2 * tq;

    uint32_t outw[4];
#pragma unroll
    for (int pos = 0; pos < 4; ++pos) {
        const int row = rbase + (pos & 1) * 8;
        const int kk = k0 + (pos >> 1) * 8;
        const int j = row >> 2, gate = row & 3;
        const float* wrow = w + (size_t)(gate * HH + j) * HH;
        outw[pos] = pack2h(wrow[kk], wrow[kk + 1]);
    }
    g_ap[id] = make_uint4(outw[0], outw[1], outw[2], outw[3]);
}

// ---------------------------------------------------------------------------
// Merged prepack: x A-fragments, w_ih B-fragments, h/counter init.
// 2^21 threads.
// ---------------------------------------------------------------------------
__global__ void prepack_misc(const float* __restrict__ x,
                             const float* __restrict__ wih_f,
                             const float* __restrict__ wih_r) {
    const int id = blockIdx.x * blockDim.x + threadIdx.x;

    // Task 1: x -> A fragments (1,024,000 threads)
    if (id < 1000 * 32 * 32) {
        const int lane = id & 31;
        const int kA = (id >> 5) & 31;
        const int mt = id >> 10;
        const int g = lane >> 2, tq = lane & 3;
        const int m0 = mt * 16 + g;
        const int k0 = kA * 16 + 2 * tq;
        uint32_t outw[4];
#pragma unroll
        for (int pos = 0; pos < 4; ++pos) {
            const int m = m0 + (pos & 1) * 8;
            const int kk = k0 + (pos >> 1) * 8;
            const float* xr = x + (size_t)m * INF;
            outw[pos] = pack2h(xr[kk], xr[kk + 1]);
        }
        g_xa[id] = make_uint4(outw[0], outw[1], outw[2], outw[3]);
    }

    // Task 2: w_ih -> B fragments (2^21 words)
    {
        const int sub = id & 3;
        const int laneW = (id >> 2) & 31;
        const int half = (id >> 7) & 1;
        const int kA = (id >> 8) & 31;
        const int nt = (id >> 13) & 127;
        const int dir = id >> 20;
        const float* __restrict__ w = dir ? wih_r : wih_f;
        const int wd = half * 4 + sub;
        const int ip = (wd & 1) * 4 + (laneW & 3);
        const int nl = (wd >> 1) * 8 + (laneW >> 2);
        const int n = nt * 32 + nl;
        const int k = kA * 16 + ip * 2;
        const float* wr = w + (size_t)n * INF;
        reinterpret_cast<uint32_t*>(g_wb)[id] = pack2h(wr[k], wr[k + 1]);
    }

    // Task 3: init h fragments + counters
    if (id < 2 * 2 * 64 * 2 * 32) g_hp[id] = make_uint4(0u, 0u, 0u, 0u);
    if (id < 2 * 32) g_cnt[id] = 0u;
}

// ---------------------------------------------------------------------------
// gx GEMM via fp16 mma.sync; epilogue stores PACKED FP16 gx (proven).
// ---------------------------------------------------------------------------
__global__ void __launch_bounds__(256)
gemm_gx(const float* __restrict__ bih_f, const float* __restrict__ bhh_f,
        const float* __restrict__ bih_r, const float* __restrict__ bhh_r) {
    extern __shared__ uint4 sm[];
    const uint32_t sbase = smaddr(sm);

    const int tid = threadIdx.x;
    const int lane = tid & 31;
    const int wid = tid >> 5;
    const int mw = wid >> 2, nw = wid & 3;
    const int dir = blockIdx.x >> 5;
    const int nti = blockIdx.x & 31;
    const int mt0 = blockIdx.y * 8;
    const int nt0 = nti * 4;

    const float* __restrict__ b1 = dir ? bih_r : bih_f;
    const float* __restrict__ b2 = dir ? bhh_r : bhh_f;
    uint32_t* __restrict__ gxw =
        reinterpret_cast<uint32_t*>(g_gxh) + (size_t)dir * TT * BB * 2048;

    auto load_chunk = [&](int c, int buf) {
        const int kA0 = c * 8;
#pragma unroll
        for (int i = 0; i < 8; ++i) {
            const int idx = tid + i * 256;
            const int mtl = idx >> 8;
            const int kAl = (idx >> 5) & 7;
            const int l = idx & 31;
            const uint4* src = g_xa + ((size_t)(mt0 + mtl) * 32 + kA0 + kAl) * 32 + l;
            cpa16(sbase + (buf * 2048 + idx) * 16, src);
        }
#pragma unroll
        for (int i = 0; i < 8; ++i) {
            const int idx = tid + i * 256;
            const int ntl = idx >> 9;
            const int kAl = (idx >> 6) & 7;
            const int hf = (idx >> 5) & 1;
            const int l = idx & 31;
            const uint4* src =
                g_wb + ((((size_t)(dir * 128 + nt0 + ntl) * 32 + kA0 + kAl) * 2 + hf)) * 32 + l;
            cpa16(sbase + (4096 + buf * 2048 + idx) * 16, src);
        }
        cpa_commit();
    };

    float acc[4][4][4] = {};

    load_chunk(0, 0);
    load_chunk(1, 1);

#pragma unroll 1
    for (int c = 0; c < 4; ++c) {
        cpa_wait<1>();
        __syncthreads();
        const int buf = c & 1;
        const uint4* Asm = sm + buf * 2048;
        const uint4* Bsm = sm + 4096 + buf * 2048;
#pragma unroll
        for (int kAl = 0; kAl < 8; ++kAl) {
            uint4 af[4];
#pragma unroll
            for (int i = 0; i < 4; ++i)
                af[i] = Asm[((mw * 4 + i) * 8 + kAl) * 32 + lane];
            uint4 bf0 = Bsm[((nw * 8 + kAl) * 2 + 0) * 32 + lane];
            uint4 bf1 = Bsm[((nw * 8 + kAl) * 2 + 1) * 32 + lane];
#pragma unroll
            for (int i = 0; i < 4; ++i) {
                mma16816(acc[i][0], af[i], bf0.x, bf0.y);
                mma16816(acc[i][1], af[i], bf0.z, bf0.w);
                mma16816(acc[i][2], af[i], bf1.x, bf1.y);
                mma16816(acc[i][3], af[i], bf1.z, bf1.w);
            }
        }
        __syncthreads();
        if (c + 2 < 4) load_chunk(c + 2, buf);
    }

    const int g = lane >> 2, q = lane & 3;
#pragma unroll
    for (int i = 0; i < 4; ++i) {
        const int m = blockIdx.y * 128 + mw * 64 + i * 16 + g;
#pragma unroll
        for (int nt = 0; nt < 4; ++nt) {
            const int nd = nti * 128 + nw * 32 + nt * 8 + q * 2;
            const int gate = nd >> 10;
            const int j = nd & 1023;
            const int jp = j >> 1;
            const float bias0 = __ldg(&b1[nd]) + __ldg(&b2[nd]);
            const float bias1 = __ldg(&b1[nd + 1]) + __ldg(&b2[nd + 1]);
#pragma unroll
            for (int hrow = 0; hrow < 2; ++hrow) {
                const int mm = m + hrow * 8;
                const int tt = mm >> 5, bb = mm & 31;
                gxw[(((size_t)tt * BB + bb) * 512 + jp) * 4 + gate] =
                    pack2h(acc[i][nt][hrow * 2] + bias0,
                           acc[i][nt][hrow * 2 + 1] + bias1);
            }
        }
    }
}

// ---------------------------------------------------------------------------
// Persistent weight-stationary recurrence, smem-staged SINGLE-FP16 h.
// 128 CTAs x 256 thr. Per-direction release/acquire barrier on ONE counter:
// arrivals atom.add.release.gpu; waiter polls ld.acquire.gpu on the SAME
// location (morally-strong; replaces membar+volatile of R12-R16).
// ---------------------------------------------------------------------------
#define SH_U4 4096
#define PSM_BYTES (SH_U4 * 16 + 4 * 64 * 33 * 4)

__global__ void __launch_bounds__(256, 1)
lstm_persist(float* __restrict__ out) {
    extern __shared__ uint4 sm2[];
    uint4* sH = sm2;
    float* sDf = (float*)(sm2 + SH_U4);
    const uint32_t sHaddr = smaddr(sH);

    const int tid = threadIdx.x;
    const int lane = tid & 31;
    const int wid = tid >> 5;
    const int s = wid & 3;        // K-quarter
    const int rg = wid >> 2;      // row group
    const int dir = blockIdx.x >> 6;
    const int ct = blockIdx.x & 63;

    // Load A fragments into registers once: 2 row-tiles x 16 kA.
    uint4 areg[2][16];
#pragma unroll
    for (int i2 = 0; i2 < 2; ++i2) {
        const int mtl = rg * 2 + i2;
        const uint4* Ap =
            g_ap + (((size_t)(dir * 256 + ct * 4 + mtl) * 64) + s * 16) * 32 + lane;
#pragma unroll
        for (int kl = 0; kl < 16; ++kl) areg[i2][kl] = __ldg(Ap + kl * 32);
    }

    // Epilogue slot: thread -> (jpair jp, batch eb).
    const int eb = tid & 31;
    const int jp = tid >> 5;
    const int jg = ct * 16 + jp * 2;
    float2 creg = make_float2(0.f, 0.f);
    float2 hlast = make_float2(0.f, 0.f);

    uint32_t* __restrict__ hpw = reinterpret_cast<uint32_t*>(g_hp);
    const uint4* __restrict__ gxd = g_gxh + (size_t)dir * TT * BB * 512;
    unsigned* __restrict__ cntp = &g_cnt[dir * 32];

    // Prefetch gx for t = 0.
    const int slotoff = ct * 8 + jp;
    uint4 gxv;
    {
        const int tr0 = dir ? (TT - 1) : 0;
        gxv = __ldg(gxd + ((size_t)tr0 * BB + eb) * 512 + slotoff);
    }

#pragma unroll 1
    for (int t = 0; t < TT; ++t) {
        const int rb = t & 1, wb = rb ^ 1;
        const int tr = dir ? (TT - 1 - t) : t;

        // Stage this warp-pair's h quarter (kA s*16..s*16+15) into smem.
        {
            const size_t gbase = (size_t)(rb * 2 + dir) * SH_U4;
            const int cbase2 = s * 1024 + rg * 512;
#pragma unroll
            for (int i = 0; i < 16; ++i) {
                const int idx = cbase2 + i * 32 + lane;
                cpa16(sHaddr + idx * 16, g_hp + gbase + idx);
            }
            cpa_commit();
            cpa_wait<0>();
            asm volatile("bar.sync %0, 64;" :: "r"(s + 1) : "memory");
        }

        float acc[2][4][4] = {};

        // MMA over 16 kA, double-buffered smem fragment loads (2 u4/kA).
        {
            const uint4* Bq = sH + s * 1024;
            uint4 pb0[2], pb1[2];
#pragma unroll
            for (int s2 = 0; s2 < 2; ++s2) pb0[s2] = Bq[s2 * 32 + lane];
#pragma unroll
            for (int kl = 0; kl < 16; ++kl) {
                uint4* cur = (kl & 1) ? pb1 : pb0;
                uint4* nxt = (kl & 1) ? pb0 : pb1;
                if (kl + 1 < 16) {
#pragma unroll
                    for (int s2 = 0; s2 < 2; ++s2)
                        nxt[s2] = Bq[(kl + 1) * 64 + s2 * 32 + lane];
                }
#pragma unroll
                for (int i2 = 0; i2 < 2; ++i2) {
                    const uint4 a = areg[i2][kl];
                    mma16816(acc[i2][0], a, cur[0].x, cur[0].y);
                    mma16816(acc[i2][1], a, cur[0].z, cur[0].w);
                    mma16816(acc[i2][2], a, cur[1].x, cur[1].y);
                    mma16816(acc[i2][3], a, cur[1].z, cur[1].w);
                }
            }
        }

        // D -> smem (4 K-slices).
        {
            const int g = lane >> 2, tq = lane & 3;
#pragma unroll
            for (int i2 = 0; i2 < 2; ++i2) {
                const int rbse = (rg * 2 + i2) * 16;
#pragma unroll
                for (int nt = 0; nt < 4; ++nt) {
                    sDf[(s * 64 + rbse + g) * 33 + nt * 8 + 2 * tq] = acc[i2][nt][0];
                    sDf[(s * 64 + rbse + g) * 33 + nt * 8 + 2 * tq + 1] = acc[i2][nt][1];
                    sDf[(s * 64 + rbse + g + 8) * 33 + nt * 8 + 2 * tq] = acc[i2][nt][2];
                    sDf[(s * 64 + rbse + g + 8) * 33 + nt * 8 + 2 * tq + 1] = acc[i2][nt][3];
                }
            }
        }
        __syncthreads();

        // Epilogue: reduce 4 K-slices, gates, cell update, write h fragments.
        {
            const int jl0 = jp * 2;
            float d[8];
#pragma unroll
            for (int q = 0; q < 8; ++q) {
                float v = 0.f;
#pragma unroll
                for (int sl = 0; sl < 4; ++sl)
                    v += sDf[(sl * 64 + jl0 * 4 + q) * 33 + eb];
                d[q] = v;
            }

            const float2 xi = h2f2(gxv.x);
            const float2 xf = h2f2(gxv.y);
            const float2 xg = h2f2(gxv.z);
            const float2 xo = h2f2(gxv.w);

            const float i0 = hsig(d[0] + xi.x);
            const float f0 = hsig(d[1] + xf.x);
            const float g0 = htanh(d[2] + xg.x);
            const float o0 = hsig(d[3] + xo.x);
            const float c0 = f0 * creg.x + i0 * g0;
            const float h0 = o0 * htanh(c0);

            const float i1 = hsig(d[4] + xi.y);
            const float f1 = hsig(d[5] + xf.y);
            const float g1 = htanh(d[6] + xg.y);
            const float o1 = hsig(d[7] + xo.y);
            const float c1 = f1 * creg.y + i1 * g1;
            const float h1 = o1 * htanh(c1);

            creg = make_float2(c0, c1);
            hlast = make_float2(h0, h1);

            // h -> fp16 B-fragment (peers' critical path; before the release).
            const uint32_t hiw = pack2h(h0, h1);
            const int ks = jg >> 4;
            const int rem = jg & 15;
            const int laneW = (eb & 7) * 4 + ((rem >> 1) & 3);
            const int word = (eb >> 3) * 2 + ((rem >> 3) & 1);
            const int half = word >> 2, sub = word & 3;
            const size_t base =
                ((((size_t)(wb * 2 + dir) * 64 + ks) * 2 + half) * 32 + laneW) * 4 + sub;
            hpw[base] = hiw;
        }

        // Barrier: sync (orders all threads' h-stores before tid0's release),
        // release arrival, poll-shadow work, acquire poll, sync broadcast.
        __syncthreads();
        if (tid == 0) arrive_release(cntp);

        // Poll-shadow work (feeds nobody this step):
        *(float2*)&out[((size_t)tr * BB + eb) * H2 + dir * HH + jg] = hlast;
        {
            const int tn = (t + 1 < TT) ? t + 1 : t;
            const int trn = dir ? (TT - 1 - tn) : tn;
            gxv = __ldg(gxd + ((size_t)trn * BB + eb) * 512 + slotoff);
        }

        if (tid == 0) {
            const unsigned target = 64u * (unsigned)(t + 1);
            while (ld_acquire(cntp) < target) {}
        }
        __syncthreads();
    }

    // hy / cy tail.
    {
        const size_t obase = (size_t)TT * BB * H2;
        *(float2*)&out[obase + ((size_t)dir * BB + eb) * HH + jg] = hlast;
        *(float2*)&out[obase + 2 * BB * HH + ((size_t)dir * BB + eb) * HH + jg] = creg;
    }
}

// ---------------------------------------------------------------------------
extern "C" void kernel_launch(void* const* d_in, const int* in_sizes, int n_in,
                              void* d_out, int out_size) {
    const float* x     = (const float*)d_in[0];
    const float* wih_f = (const float*)d_in[1];
    const float* whh_f = (const float*)d_in[2];
    const float* bih_f = (const float*)d_in[3];
    const float* bhh_f = (const float*)d_in[4];
    const float* wih_r = (const float*)d_in[5];
    const float* whh_r = (const float*)d_in[6];
    const float* bih_r = (const float*)d_in[7];
    const float* bhh_r = (const float*)d_in[8];
    float* out = (float*)d_out;

    const int gemm_smem = 8192 * 16;  // 128 KB
    cudaFuncSetAttribute(gemm_gx,
                         cudaFuncAttributeMaxDynamicSharedMemorySize, gemm_smem);
    cudaFuncSetAttribute(lstm_persist,
                         cudaFuncAttributeMaxDynamicSharedMemorySize, PSM_BYTES);

    prepack_a<<<4096, 256>>>(whh_f, whh_r);
    prepack_misc<<<8192, 256>>>(x, wih_f, wih_r);

    gemm_gx<<<dim3(64, 125), 256, gemm_smem>>>(bih_f, bhh_f, bih_r, bhh_r);

    lstm_persist<<<NBLK2, 256, PSM_BYTES>>>(out);
}